// round 9
// baseline (speedup 1.0000x reference)
#include <cuda_runtime.h>
#include <cstdint>

// Sepconv: out[b,c,y,x] = sum_{i,j} in[b,c,5y+i,5x+j] * V[b,i,y,x] * H[b,j,y,x]
// B=8, C=3, F=5, HO=WO=256. HBM-bound: 184.6 MB compulsory traffic.
//
// R9 (convergence): R8's TMA-bulk structure — measured at the chip's
// path-independent ~6.15 TB/s LTS/DRAM ceiling (ncu dur == bytes/BW) — with
// the 15 bulk-copy posts spread across 3 lanes (one channel each) so the
// last channel's loads enter the TMA queue ~3x sooner per CTA.

#define B_ 8
#define C_ 3
#define F_ 5
#define HO_ 256
#define WO_ 256
#define HI_ (HO_ * F_)
#define WI_ (WO_ * F_)

#define HALF_W   128
#define STRIP_W  (HALF_W * F_)            // 640 floats per row chunk
#define ROW_BYTES (STRIP_W * 4)           // 2560 B per bulk copy
#define TILE_FLOATS (F_ * STRIP_W)        // 3200 floats = 12.8 KB per strip
#define TILE_BYTES  (TILE_FLOATS * 4)     // 12800
#define NT 128

__device__ __forceinline__ void mbar_init(uint32_t mbar, uint32_t count) {
    asm volatile("mbarrier.init.shared.b64 [%0], %1;\n"
                 :: "r"(mbar), "r"(count) : "memory");
}
__device__ __forceinline__ void mbar_expect_tx(uint32_t mbar, uint32_t bytes) {
    asm volatile("mbarrier.arrive.expect_tx.shared.b64 _, [%0], %1;\n"
                 :: "r"(mbar), "r"(bytes) : "memory");
}
__device__ __forceinline__ void bulk_cp(uint32_t dst, const void* src,
                                        uint32_t bytes, uint32_t mbar) {
    asm volatile(
        "cp.async.bulk.shared::cta.global.mbarrier::complete_tx::bytes "
        "[%0], [%1], %2, [%3];\n"
        :: "r"(dst), "l"(src), "r"(bytes), "r"(mbar) : "memory");
}
__device__ __forceinline__ void mbar_wait(uint32_t mbar, uint32_t parity) {
    asm volatile(
        "{\n\t"
        ".reg .pred P;\n\t"
        "WAIT_%=:\n\t"
        "mbarrier.try_wait.parity.acquire.cta.shared::cta.b64 P, [%0], %1, 0x989680;\n\t"
        "@!P bra WAIT_%=;\n\t"
        "}"
        :: "r"(mbar), "r"(parity) : "memory");
}

__global__ __launch_bounds__(NT) void sepconv_tma9_kernel(
    const float* __restrict__ in,
    const float* __restrict__ V,
    const float* __restrict__ H,
    float* __restrict__ out)
{
    __shared__ __align__(16) float sdata[C_ * TILE_FLOATS];   // 38.4 KB
    __shared__ __align__(8) unsigned long long mbar[C_];

    const int tid  = threadIdx.x;        // 0..127
    const int half = blockIdx.x & 1;
    const int y    = (blockIdx.x >> 1) & (HO_ - 1);
    const int b    = blockIdx.x >> 9;
    const int x0   = half * HALF_W;

    const uint32_t sdata_u = (uint32_t)__cvta_generic_to_shared(sdata);
    const uint32_t mbar_u  = (uint32_t)__cvta_generic_to_shared(mbar);

    if (tid == 0) {
#pragma unroll
        for (int c = 0; c < C_; c++)
            mbar_init(mbar_u + 8u * c, 1);
        // Make generic-proxy mbarrier init visible to the async proxy.
        asm volatile("fence.proxy.async.shared::cta;\n" ::: "memory");
    }
    __syncthreads();

    // Lanes 0..2 each post one channel's 5 bulk copies (parallel posting).
    if (tid < C_) {
        const int c = tid;
        const long long base0 = ((long long)(b * C_) * HI_ + (long long)y * F_) * WI_
                                + (long long)half * STRIP_W;
        mbar_expect_tx(mbar_u + 8u * c, TILE_BYTES);
        const float* strip = in + base0 + (long long)c * HI_ * WI_;
        const uint32_t dst = sdata_u + (uint32_t)(c * TILE_BYTES);
#pragma unroll
        for (int r = 0; r < F_; r++)
            bulk_cp(dst + (uint32_t)(r * ROW_BYTES),
                    strip + r * WI_, ROW_BYTES, mbar_u + 8u * c);
    }

    // Weights for (b, y, x0+tid): coalesced, overlap with TMA in flight.
    float v[F_], h[F_];
    {
        const int sb = (b * F_) * (HO_ * WO_) + y * WO_ + x0 + tid;
#pragma unroll
        for (int i = 0; i < F_; i++) {
            v[i] = V[sb + i * (HO_ * WO_)];
            h[i] = H[sb + i * (HO_ * WO_)];
        }
    }

#pragma unroll
    for (int c = 0; c < C_; c++) {
        mbar_wait(mbar_u + 8u * c, 0);            // acquire: strip c ready

        const float* s = sdata + c * TILE_FLOATS;
        float acc = 0.0f;
#pragma unroll
        for (int i = 0; i < F_; i++) {
            const float* row = s + i * STRIP_W + tid * F_;
            float rs = 0.0f;
#pragma unroll
            for (int j = 0; j < F_; j++)
                rs = fmaf(row[j], h[j], rs);
            acc = fmaf(rs, v[i], acc);
        }
        __stcs(out + ((b * C_ + c) * HO_ + y) * WO_ + x0 + tid, acc);
    }
}

extern "C" void kernel_launch(void* const* d_in, const int* in_sizes, int n_in,
                              void* d_out, int out_size)
{
    const float* in  = (const float*)d_in[0];  // [8,3,1280,1280]
    const float* V   = (const float*)d_in[1];  // [8,5,256,256]
    const float* H   = (const float*)d_in[2];  // [8,5,256,256]
    float* out = (float*)d_out;                // [8,3,256,256]

    const int blocks = B_ * HO_ * 2;           // 4096: (b, y, half)
    sepconv_tma9_kernel<<<blocks, NT>>>(in, V, H, out);
}